// round 5
// baseline (speedup 1.0000x reference)
#include <cuda_runtime.h>
#include <cuda_bf16.h>
#include <cstddef>

#define N_NODES   50000
#define N_GRAPHS  128
#define IN_C      128
#define HID_C     128
#define OUT_C     64
#define E_MAX     700000

// ---------------- device scratch (no allocations allowed) ----------------
__device__ int   g_degi[N_NODES];        // in-degree (by dst)
__device__ int   g_off [N_NODES + 1];    // CSR row offsets
__device__ int   g_cur [N_NODES];        // fill cursors
__device__ int   g_csr [E_MAX];          // src id per CSR slot (grouped by dst)
__device__ float g_dinv[N_NODES];
__device__ float g_g1  [(size_t)N_NODES * HID_C];   // dinv * (x @ W1)
__device__ float g_t   [(size_t)N_NODES * HID_C];   // relu(layer1 out)
__device__ float g_g2  [(size_t)N_NODES * OUT_C];   // dinv * (t @ W2)
__device__ float g_gsum[N_GRAPHS * OUT_C];
__device__ float g_gcnt[N_GRAPHS];

__device__ __forceinline__ void red_add_v4(float* p, float4 v) {
    asm volatile("red.global.add.v4.f32 [%0], {%1, %2, %3, %4};"
                 :: "l"(p), "f"(v.x), "f"(v.y), "f"(v.z), "f"(v.w)
                 : "memory");
}
__device__ __forceinline__ float4 f4add(float4 a, float4 b) {
    return make_float4(a.x + b.x, a.y + b.y, a.z + b.z, a.w + b.w);
}

// ---------------- degree (by dst) ----------------
__global__ void deg_kernel(const int* __restrict__ dst, int E) {
    int e = blockIdx.x * blockDim.x + threadIdx.x;
    if (e < E) atomicAdd(&g_degi[dst[e]], 1);
}

// ---------------- exclusive scan of degrees + dinv (single block, 1024 thr) ----------------
__global__ void scan_kernel(int N) {
    __shared__ int ssum[1024];
    const int tid = threadIdx.x;
    const int C   = (N + 1023) / 1024;
    const int lo  = tid * C;
    const int hi  = min(lo + C, N);

    int s = 0;
    for (int i = lo; i < hi; i++) s += g_degi[i];
    ssum[tid] = s;
    __syncthreads();
    // inclusive Hillis-Steele
    for (int off = 1; off < 1024; off <<= 1) {
        int v = (tid >= off) ? ssum[tid - off] : 0;
        __syncthreads();
        ssum[tid] += v;
        __syncthreads();
    }
    int running = ssum[tid] - s;   // exclusive base for this chunk
    for (int i = lo; i < hi; i++) {
        g_off[i] = running;
        g_cur[i] = running;
        int d = g_degi[i];
        g_dinv[i] = rsqrtf((float)(1 + d));   // +1 self-loop
        running += d;
    }
    if (tid == 1023) g_off[N] = ssum[1023];
}

// ---------------- CSR fill: bucket srcs by dst ----------------
__global__ void fill_kernel(const int* __restrict__ src,
                            const int* __restrict__ dst,
                            int E) {
    int e = blockIdx.x * blockDim.x + threadIdx.x;
    if (e < E) {
        int d = dst[e];
        int pos = atomicAdd(&g_cur[d], 1);
        g_csr[pos] = src[e];
    }
}

// ---------------- GEMM1: g1 = dinv ⊙ (X @ W1)  [M,128]x[128,128] ----------------
__global__ void gemm1_kernel(const float* __restrict__ X,
                             const float* __restrict__ W,
                             int M) {
    __shared__ __align__(16) float xs[16][68];
    __shared__ __align__(16) float ws[16][128];

    const int tid = threadIdx.x;
    const int tn  = tid & 15;
    const int tm  = tid >> 4;
    const int row0 = blockIdx.x * 64;

    float acc[4][8];
#pragma unroll
    for (int m = 0; m < 4; m++)
#pragma unroll
        for (int n = 0; n < 8; n++) acc[m][n] = 0.f;

    const int lm = tid >> 2;
    const int lk = (tid & 3) * 4;

    for (int k0 = 0; k0 < IN_C; k0 += 16) {
        {
            int row = row0 + lm;
            float4 v = make_float4(0.f, 0.f, 0.f, 0.f);
            if (row < M)
                v = *(const float4*)(X + (size_t)row * IN_C + k0 + lk);
            xs[lk + 0][lm] = v.x;
            xs[lk + 1][lm] = v.y;
            xs[lk + 2][lm] = v.z;
            xs[lk + 3][lm] = v.w;
        }
#pragma unroll
        for (int i = 0; i < 2; i++) {
            int idx4 = tid + i * 256;
            int k  = idx4 >> 5;
            int n4 = idx4 & 31;
            *(float4*)(&ws[k][n4 * 4]) =
                *(const float4*)(W + (size_t)(k0 + k) * HID_C + n4 * 4);
        }
        __syncthreads();

#pragma unroll
        for (int k = 0; k < 16; k++) {
            float xr[4], wr[8];
#pragma unroll
            for (int m = 0; m < 4; m++) xr[m] = xs[k][tm * 4 + m];
#pragma unroll
            for (int n = 0; n < 8; n++) wr[n] = ws[k][tn * 8 + n];
#pragma unroll
            for (int m = 0; m < 4; m++)
#pragma unroll
                for (int n = 0; n < 8; n++) acc[m][n] += xr[m] * wr[n];
        }
        __syncthreads();
    }

#pragma unroll
    for (int m = 0; m < 4; m++) {
        int row = row0 + tm * 4 + m;
        if (row < M) {
            float d = g_dinv[row];
            float* out = g_g1 + (size_t)row * HID_C + tn * 8;
#pragma unroll
            for (int n = 0; n < 8; n++) out[n] = d * acc[m][n];
        }
    }
}

// ---------------- gather layer 1 (pull) + fused relu/bias: t = relu(dinv*(Σ g1[s] + g1[d]) + b1) ----------------
// one warp per dst node; lane holds float4 (128 floats/row)
__global__ void gather1_kernel(const float* __restrict__ b1, int N) {
    int node = blockIdx.x * 8 + (threadIdx.x >> 5);
    int lane = threadIdx.x & 31;
    if (node >= N) return;

    int e  = g_off[node];
    int e1 = g_off[node + 1];

    // self-loop term
    float4 v0 = ((const float4*)(g_g1 + (size_t)node * HID_C))[lane];
    float4 v1 = make_float4(0.f, 0.f, 0.f, 0.f);

    // unroll 2 for MLP
    for (; e + 1 < e1; e += 2) {
        int s0 = g_csr[e];
        int s1 = g_csr[e + 1];
        float4 a = ((const float4*)(g_g1 + (size_t)s0 * HID_C))[lane];
        float4 b = ((const float4*)(g_g1 + (size_t)s1 * HID_C))[lane];
        v0 = f4add(v0, a);
        v1 = f4add(v1, b);
    }
    if (e < e1) {
        int s0 = g_csr[e];
        v0 = f4add(v0, ((const float4*)(g_g1 + (size_t)s0 * HID_C))[lane]);
    }
    float4 v = f4add(v0, v1);

    float dv = g_dinv[node];
    float4 bb = *(const float4*)(b1 + lane * 4);
    float4 r;
    r.x = fmaxf(dv * v.x + bb.x, 0.f);
    r.y = fmaxf(dv * v.y + bb.y, 0.f);
    r.z = fmaxf(dv * v.z + bb.z, 0.f);
    r.w = fmaxf(dv * v.w + bb.w, 0.f);
    ((float4*)(g_t + (size_t)node * HID_C))[lane] = r;
}

// ---------------- GEMM2: g2 = dinv ⊙ (t @ W2)  [M,128]x[128,64] ----------------
__global__ void gemm2_kernel(const float* __restrict__ W2, int M) {
    __shared__ __align__(16) float xs[16][68];
    __shared__ __align__(16) float ws[16][64];

    const int tid = threadIdx.x;
    const int tn  = tid & 15;
    const int tm  = tid >> 4;
    const int row0 = blockIdx.x * 64;

    float acc[4][4];
#pragma unroll
    for (int m = 0; m < 4; m++)
#pragma unroll
        for (int n = 0; n < 4; n++) acc[m][n] = 0.f;

    const int lm = tid >> 2;
    const int lk = (tid & 3) * 4;

    for (int k0 = 0; k0 < HID_C; k0 += 16) {
        {
            int row = row0 + lm;
            float4 r = make_float4(0.f, 0.f, 0.f, 0.f);
            if (row < M)
                r = *(const float4*)(g_t + (size_t)row * HID_C + k0 + lk);
            xs[lk + 0][lm] = r.x;
            xs[lk + 1][lm] = r.y;
            xs[lk + 2][lm] = r.z;
            xs[lk + 3][lm] = r.w;
        }
        {
            int k  = tid >> 4;
            int n4 = tid & 15;
            *(float4*)(&ws[k][n4 * 4]) =
                *(const float4*)(W2 + (size_t)(k0 + k) * OUT_C + n4 * 4);
        }
        __syncthreads();

#pragma unroll
        for (int k = 0; k < 16; k++) {
            float xr[4], wr[4];
#pragma unroll
            for (int m = 0; m < 4; m++) xr[m] = xs[k][tm * 4 + m];
#pragma unroll
            for (int n = 0; n < 4; n++) wr[n] = ws[k][tn * 4 + n];
#pragma unroll
            for (int m = 0; m < 4; m++)
#pragma unroll
                for (int n = 0; n < 4; n++) acc[m][n] += xr[m] * wr[n];
        }
        __syncthreads();
    }

#pragma unroll
    for (int m = 0; m < 4; m++) {
        int row = row0 + tm * 4 + m;
        if (row < M) {
            float d = g_dinv[row];
            float* out = g_g2 + (size_t)row * OUT_C + tn * 4;
#pragma unroll
            for (int n = 0; n < 4; n++) out[n] = d * acc[m][n];
        }
    }
}

// ---------------- gather layer 2 (pull) + fused bias + pool RED ----------------
// 16-lane group per dst node; lane holds float4 (64 floats/row)
__global__ void gather2_kernel(const int* __restrict__ batch,
                               const float* __restrict__ b2, int N) {
    int node = blockIdx.x * 16 + (threadIdx.x >> 4);
    int lane = threadIdx.x & 15;
    if (node >= N) return;

    int e  = g_off[node];
    int e1 = g_off[node + 1];

    float4 v0 = ((const float4*)(g_g2 + (size_t)node * OUT_C))[lane];  // self
    float4 v1 = make_float4(0.f, 0.f, 0.f, 0.f);

    for (; e + 1 < e1; e += 2) {
        int s0 = g_csr[e];
        int s1 = g_csr[e + 1];
        float4 a = ((const float4*)(g_g2 + (size_t)s0 * OUT_C))[lane];
        float4 b = ((const float4*)(g_g2 + (size_t)s1 * OUT_C))[lane];
        v0 = f4add(v0, a);
        v1 = f4add(v1, b);
    }
    if (e < e1) {
        int s0 = g_csr[e];
        v0 = f4add(v0, ((const float4*)(g_g2 + (size_t)s0 * OUT_C))[lane]);
    }
    float4 v = f4add(v0, v1);

    float dv = g_dinv[node];
    float4 bb = *(const float4*)(b2 + lane * 4);
    float4 r;
    r.x = dv * v.x + bb.x;
    r.y = dv * v.y + bb.y;
    r.z = dv * v.z + bb.z;
    r.w = dv * v.w + bb.w;

    int b = batch[node];
    red_add_v4(g_gsum + b * OUT_C + lane * 4, r);
    if (lane == 0) atomicAdd(&g_gcnt[b], 1.0f);
}

__global__ void divide_kernel(float* __restrict__ out, int G) {
    int i = blockIdx.x * blockDim.x + threadIdx.x;
    if (i < G * OUT_C) {
        float c = g_gcnt[i / OUT_C];
        out[i] = g_gsum[i] / fmaxf(c, 1.0f);
    }
}

// ---------------- launch ----------------
extern "C" void kernel_launch(void* const* d_in, const int* in_sizes, int n_in,
                              void* d_out, int out_size) {
    const float* x   = (const float*)d_in[0];
    const float* W1  = (const float*)d_in[1];
    const float* b1  = (const float*)d_in[2];
    const float* W2  = (const float*)d_in[3];
    const float* b2  = (const float*)d_in[4];
    const int*   ei  = (const int*)d_in[5];   // int32
    const int*   bat = (const int*)d_in[6];

    const int N = in_sizes[0] / IN_C;      // 50000
    const int E = in_sizes[5] / 2;         // 625000
    const int G = out_size / OUT_C;        // 128

    const int* src = ei;
    const int* dst = ei + E;

    void *p_degi, *p_gsum, *p_gcnt;
    cudaGetSymbolAddress(&p_degi, g_degi);
    cudaGetSymbolAddress(&p_gsum, g_gsum);
    cudaGetSymbolAddress(&p_gcnt, g_gcnt);

    cudaMemsetAsync(p_degi, 0, (size_t)N * sizeof(int));
    cudaMemsetAsync(p_gsum, 0, (size_t)G * OUT_C * sizeof(float));
    cudaMemsetAsync(p_gcnt, 0, (size_t)G * sizeof(float));

    deg_kernel <<<(E + 255) / 256, 256>>>(dst, E);
    scan_kernel<<<1, 1024>>>(N);                      // offsets + cursors + dinv
    fill_kernel<<<(E + 255) / 256, 256>>>(src, dst, E);

    gemm1_kernel  <<<(N + 63) / 64, 256>>>(x, W1, N);
    gather1_kernel<<<(N + 7) / 8, 256>>>(b1, N);      // 1 warp/node

    gemm2_kernel  <<<(N + 63) / 64, 256>>>(W2, N);
    gather2_kernel<<<(N + 15) / 16, 256>>>(bat, b2, N); // 16 lanes/node

    divide_kernel<<<(G * OUT_C + 255) / 256, 256>>>((float*)d_out, G);
}

// round 6
// speedup vs baseline: 1.4257x; 1.4257x over previous
#include <cuda_runtime.h>
#include <cuda_bf16.h>
#include <mma.h>
#include <cstddef>

using namespace nvcuda;

#define N_NODES   50000
#define N_GRAPHS  128
#define IN_C      128
#define HID_C     128
#define OUT_C     64

// ---------------- device scratch (no allocations allowed) ----------------
__device__ int   g_degi[N_NODES];
__device__ float g_dinv[N_NODES];
__device__ float g_g1  [(size_t)N_NODES * HID_C];   // dinv * (x @ W1)
__device__ float g_acc1[(size_t)N_NODES * HID_C];   // scatter accumulator layer 1
__device__ float g_g2  [(size_t)N_NODES * OUT_C];   // dinv * (t @ W2)
__device__ float g_acc2[(size_t)N_NODES * OUT_C];   // scatter accumulator layer 2
__device__ float g_gsum[N_GRAPHS * OUT_C];
__device__ float g_gcnt[N_GRAPHS];

__device__ __forceinline__ void red_add_v4(float* p, float4 v) {
    asm volatile("red.global.add.v4.f32 [%0], {%1, %2, %3, %4};"
                 :: "l"(p), "f"(v.x), "f"(v.y), "f"(v.z), "f"(v.w)
                 : "memory");
}

// ---------------- degree / dinv ----------------
__global__ void deg_kernel(const int* __restrict__ dst, int E) {
    int e = blockIdx.x * blockDim.x + threadIdx.x;
    if (e < E) atomicAdd(&g_degi[dst[e]], 1);
}

__global__ void dinv_kernel(int N) {
    int i = blockIdx.x * blockDim.x + threadIdx.x;
    if (i < N) g_dinv[i] = rsqrtf((float)(1 + g_degi[i]));  // +1 self-loop
}

// ---------------- 3xTF32 tensor-core GEMM ----------------
// C[M,BN] = dinv ⊙ (A[M,128] @ B[128,BN]); BM=64/block, 256 threads (8 warps).
// Warp w: m_tile = w>>1 (16 rows), n_group = w&1 (BN/2 cols = NT tiles of 16).
// FUSE_IN: A row built on the fly = relu(dinv*(acc1+g1)+bias)  (layer-2 input).
template<int BN, bool FUSE_IN>
__global__ void gemm_tf32_kernel(const float* __restrict__ A,
                                 const float* __restrict__ bias,
                                 const float* __restrict__ B,
                                 float* __restrict__ C, int M) {
    extern __shared__ float smem[];
    float* As = smem;                      // [64][132]
    float* Bs = smem + 64 * 132;           // [128][BN+4]
    constexpr int LDB = BN + 4;
    constexpr int NT  = BN / 32;           // 16-wide n-tiles per warp

    const int tid  = threadIdx.x;
    const int wid  = tid >> 5;
    const int lane = tid & 31;
    const int row0 = blockIdx.x * 64;
    const int m_tile  = wid >> 1;
    const int n_group = wid & 1;

    // stage B (whole 128 x BN weight matrix)
    constexpr int BF4 = BN / 4;
    for (int idx = tid; idx < 128 * BF4; idx += 256) {
        int r = idx / BF4, c4 = idx % BF4;
        *(float4*)(Bs + r * LDB + c4 * 4) = *(const float4*)(B + (size_t)r * BN + c4 * 4);
    }
    // stage A tile [64][128]
    for (int idx = tid; idx < 64 * 32; idx += 256) {
        int r = idx >> 5, c4 = idx & 31;
        int grow = row0 + r;
        float4 v = make_float4(0.f, 0.f, 0.f, 0.f);
        if (grow < M) {
            if (FUSE_IN) {
                float dv = g_dinv[grow];
                float4 av = ((const float4*)(g_acc1 + (size_t)grow * 128))[c4];
                float4 gv = ((const float4*)(g_g1   + (size_t)grow * 128))[c4];
                float4 bv = ((const float4*)bias)[c4];
                v.x = fmaxf(dv * (av.x + gv.x) + bv.x, 0.f);
                v.y = fmaxf(dv * (av.y + gv.y) + bv.y, 0.f);
                v.z = fmaxf(dv * (av.z + gv.z) + bv.z, 0.f);
                v.w = fmaxf(dv * (av.w + gv.w) + bv.w, 0.f);
            } else {
                v = *(const float4*)(A + (size_t)grow * 128 + c4 * 4);
            }
        }
        *(float4*)(As + r * 132 + c4 * 4) = v;
    }
    __syncthreads();

    wmma::fragment<wmma::accumulator, 16, 16, 8, float> acc[NT];
#pragma unroll
    for (int i = 0; i < NT; i++) wmma::fill_fragment(acc[i], 0.f);

    for (int k0 = 0; k0 < 128; k0 += 8) {
        wmma::fragment<wmma::matrix_a, 16, 16, 8, wmma::precision::tf32, wmma::row_major> a, ahi, alo;
        wmma::load_matrix_sync(a, As + m_tile * 16 * 132 + k0, 132);
#pragma unroll
        for (int i = 0; i < a.num_elements; i++) {
            float v = a.x[i];
            float h = wmma::__float_to_tf32(v);
            ahi.x[i] = h;
            alo.x[i] = wmma::__float_to_tf32(v - h);
        }
#pragma unroll
        for (int nt = 0; nt < NT; nt++) {
            int ncol = n_group * (BN / 2) + nt * 16;
            wmma::fragment<wmma::matrix_b, 16, 16, 8, wmma::precision::tf32, wmma::row_major> b, bhi, blo;
            wmma::load_matrix_sync(b, Bs + k0 * LDB + ncol, LDB);
#pragma unroll
            for (int i = 0; i < b.num_elements; i++) {
                float v = b.x[i];
                float h = wmma::__float_to_tf32(v);
                bhi.x[i] = h;
                blo.x[i] = wmma::__float_to_tf32(v - h);
            }
            wmma::mma_sync(acc[nt], alo, bhi, acc[nt]);
            wmma::mma_sync(acc[nt], ahi, blo, acc[nt]);
            wmma::mma_sync(acc[nt], ahi, bhi, acc[nt]);
        }
    }
    __syncthreads();   // done with As/Bs; reuse As as per-warp staging

    float* wbuf = smem + wid * 256;   // 16x16 per warp
#pragma unroll
    for (int nt = 0; nt < NT; nt++) {
        wmma::store_matrix_sync(wbuf, acc[nt], 16, wmma::mem_row_major);
        __syncwarp();
        int r = lane >> 1;
        int c = (lane & 1) * 8;
        int grow = row0 + m_tile * 16 + r;
        if (grow < M) {
            float d = g_dinv[grow];
            int ncol = n_group * (BN / 2) + nt * 16 + c;
            float* out = C + (size_t)grow * BN + ncol;
#pragma unroll
            for (int j = 0; j < 8; j++) out[j] = d * wbuf[r * 16 + c + j];
        }
        __syncwarp();
    }
}

// ---------------- scatter layer 1: acc1[dst] += g1[src] (128 floats/edge) ----------------
__global__ void scatter1_kernel(const int* __restrict__ src,
                                const int* __restrict__ dst,
                                int E) {
    int warp = (blockIdx.x * blockDim.x + threadIdx.x) >> 5;
    int lane = threadIdx.x & 31;
    if (warp >= E) return;
    int s = src[warp];
    int d = dst[warp];
    float4 v = ((const float4*)(g_g1 + (size_t)s * HID_C))[lane];
    red_add_v4(g_acc1 + (size_t)d * HID_C + lane * 4, v);
}

// ---------------- scatter layer 2: acc2[dst] += g2[src] (64 floats/edge) ----------------
__global__ void scatter2_kernel(const int* __restrict__ src,
                                const int* __restrict__ dst,
                                int E) {
    int t = blockIdx.x * blockDim.x + threadIdx.x;
    int e = t >> 4;
    int lane = t & 15;
    if (e >= E) return;
    int s = src[e];
    int d = dst[e];
    float4 v = ((const float4*)(g_g2 + (size_t)s * OUT_C))[lane];
    red_add_v4(g_acc2 + (size_t)d * OUT_C + lane * 4, v);
}

// ---------------- pool: out2 = dinv*(acc2+g2)+b2; RED into graph sums ----------------
__global__ void pool_kernel(const int* __restrict__ batch,
                            const float* __restrict__ b2,
                            int N) {
    int t = blockIdx.x * blockDim.x + threadIdx.x;
    int node = t >> 4;
    int lane = t & 15;
    if (node >= N) return;
    int b = batch[node];
    float dv = g_dinv[node];
    float4 av = ((const float4*)(g_acc2 + (size_t)node * OUT_C))[lane];
    float4 gv = ((const float4*)(g_g2   + (size_t)node * OUT_C))[lane];
    float4 bv = *(const float4*)(b2 + lane * 4);
    float4 r;
    r.x = dv * (av.x + gv.x) + bv.x;
    r.y = dv * (av.y + gv.y) + bv.y;
    r.z = dv * (av.z + gv.z) + bv.z;
    r.w = dv * (av.w + gv.w) + bv.w;
    red_add_v4(g_gsum + b * OUT_C + lane * 4, r);
    if (lane == 0) atomicAdd(&g_gcnt[b], 1.0f);
}

__global__ void divide_kernel(float* __restrict__ out, int G) {
    int i = blockIdx.x * blockDim.x + threadIdx.x;
    if (i < G * OUT_C) {
        float c = g_gcnt[i / OUT_C];
        out[i] = g_gsum[i] / fmaxf(c, 1.0f);
    }
}

// ---------------- launch ----------------
extern "C" void kernel_launch(void* const* d_in, const int* in_sizes, int n_in,
                              void* d_out, int out_size) {
    const float* x   = (const float*)d_in[0];
    const float* W1  = (const float*)d_in[1];
    const float* b1  = (const float*)d_in[2];
    const float* W2  = (const float*)d_in[3];
    const float* b2  = (const float*)d_in[4];
    const int*   ei  = (const int*)d_in[5];   // int32
    const int*   bat = (const int*)d_in[6];

    const int N = in_sizes[0] / IN_C;      // 50000
    const int E = in_sizes[5] / 2;         // 625000
    const int G = out_size / OUT_C;        // 128

    const int* src = ei;
    const int* dst = ei + E;

    void *p_degi, *p_acc1, *p_acc2, *p_gsum, *p_gcnt, *p_g1, *p_g2;
    cudaGetSymbolAddress(&p_degi, g_degi);
    cudaGetSymbolAddress(&p_acc1, g_acc1);
    cudaGetSymbolAddress(&p_acc2, g_acc2);
    cudaGetSymbolAddress(&p_gsum, g_gsum);
    cudaGetSymbolAddress(&p_gcnt, g_gcnt);
    cudaGetSymbolAddress(&p_g1, g_g1);
    cudaGetSymbolAddress(&p_g2, g_g2);

    cudaMemsetAsync(p_degi, 0, (size_t)N * sizeof(int));
    cudaMemsetAsync(p_acc1, 0, (size_t)N * HID_C * sizeof(float));
    cudaMemsetAsync(p_acc2, 0, (size_t)N * OUT_C * sizeof(float));
    cudaMemsetAsync(p_gsum, 0, (size_t)G * OUT_C * sizeof(float));
    cudaMemsetAsync(p_gcnt, 0, (size_t)G * sizeof(float));

    deg_kernel <<<(E + 255) / 256, 256>>>(dst, E);
    dinv_kernel<<<(N + 255) / 256, 256>>>(N);

    // GEMM1: g1 = dinv * (x @ W1)
    {
        const int smem_bytes = (64 * 132 + 128 * (128 + 4)) * sizeof(float);
        cudaFuncSetAttribute(gemm_tf32_kernel<128, false>,
                             cudaFuncAttributeMaxDynamicSharedMemorySize, smem_bytes);
        gemm_tf32_kernel<128, false><<<(N + 63) / 64, 256, smem_bytes>>>(
            x, nullptr, W1, (float*)p_g1, N);
    }
    scatter1_kernel<<<(E + 7) / 8, 256>>>(src, dst, E);

    // GEMM2: g2 = dinv * (relu(dinv*(acc1+g1)+b1) @ W2)  (input fused)
    {
        const int smem_bytes = (64 * 132 + 128 * (64 + 4)) * sizeof(float);
        cudaFuncSetAttribute(gemm_tf32_kernel<64, true>,
                             cudaFuncAttributeMaxDynamicSharedMemorySize, smem_bytes);
        gemm_tf32_kernel<64, true><<<(N + 63) / 64, 256, smem_bytes>>>(
            nullptr, b1, W2, (float*)p_g2, N);
    }
    scatter2_kernel<<<(E + 15) / 16, 256>>>(src, dst, E);

    pool_kernel<<<(N + 15) / 16, 256>>>(bat, b2, N);
    divide_kernel<<<(G * OUT_C + 255) / 256, 256>>>((float*)d_out, G);
}

// round 7
// speedup vs baseline: 1.7557x; 1.2315x over previous
#include <cuda_runtime.h>
#include <cuda_bf16.h>
#include <cstddef>

#define N_NODES   50000
#define N_GRAPHS  128
#define IN_C      128
#define HID_C     128
#define OUT_C     64

// ---------------- device scratch (no allocations allowed) ----------------
__device__ int   g_degi[N_NODES];
__device__ float g_dinv[N_NODES];
__device__ float g_g1  [(size_t)N_NODES * HID_C];   // dinv * (x @ W1)
__device__ float g_acc1[(size_t)N_NODES * HID_C];   // scatter accumulator layer 1
__device__ float g_g2  [(size_t)N_NODES * OUT_C];   // dinv * (t @ W2)
__device__ float g_acc2[(size_t)N_NODES * OUT_C];   // scatter accumulator layer 2
__device__ float g_gsum[N_GRAPHS * OUT_C];
__device__ float g_gcnt[N_GRAPHS];

__device__ __forceinline__ void red_add_v4(float* p, float4 v) {
    asm volatile("red.global.add.v4.f32 [%0], {%1, %2, %3, %4};"
                 :: "l"(p), "f"(v.x), "f"(v.y), "f"(v.z), "f"(v.w)
                 : "memory");
}

// ---------------- degree / dinv ----------------
__global__ void deg_kernel(const int* __restrict__ dst, int E) {
    int e = blockIdx.x * blockDim.x + threadIdx.x;
    if (e < E) atomicAdd(&g_degi[dst[e]], 1);
}

__global__ void dinv_kernel(int N) {
    int i = blockIdx.x * blockDim.x + threadIdx.x;
    if (i < N) g_dinv[i] = rsqrtf((float)(1 + g_degi[i]));  // +1 self-loop
}

// ---------------- classic double-buffered SGEMM ----------------
// C[M,BN] = dinv ⊙ (A[M,128] @ B[128,BN]).  BM=128, BK=8, 256 threads.
// Thread (tx=tid%16, ty=tid/16) computes rows ty*8..+7, cols tx*TN..+TN-1.
// FUSE_IN: A row built on the fly = relu(dinv*(acc1+g1)+bias)  (layer-2 input).
template<int BN, int TN, bool FUSE_IN>
__global__ void __launch_bounds__(256, 2)
sgemm_kernel(const float* __restrict__ A,
             const float* __restrict__ bias,
             const float* __restrict__ B,
             float* __restrict__ C, int M) {
    __shared__ __align__(16) float As[2][8][128];
    __shared__ __align__(16) float Bs[2][8][BN];

    const int tid  = threadIdx.x;
    const int tx   = tid & 15;
    const int ty   = tid >> 4;
    const int row0 = blockIdx.x * 128;

    // A-loader indices: one float4 per thread per stage
    const int am = tid >> 1;            // 0..127 row within tile
    const int ak = (tid & 1) * 4;       // k quad
    // B-loader indices
    const int bk  = (BN == 128) ? (tid >> 5) : (tid >> 4);
    const int bc4 = (BN == 128) ? (tid & 31) : (tid & 15);
    const bool bAct = (BN == 128) ? true : (tid < 128);

    float acc[8][TN];
#pragma unroll
    for (int i = 0; i < 8; i++)
#pragma unroll
        for (int j = 0; j < TN; j++) acc[i][j] = 0.f;

    // ---- global load helpers ----
    auto gloadA = [&](int k0) -> float4 {
        int grow = row0 + am;
        float4 v = make_float4(0.f, 0.f, 0.f, 0.f);
        if (grow < M) {
            if (FUSE_IN) {
                float dv = g_dinv[grow];
                float4 av = *(const float4*)(g_acc1 + (size_t)grow * 128 + k0 + ak);
                float4 gv = *(const float4*)(g_g1   + (size_t)grow * 128 + k0 + ak);
                float4 bv = *(const float4*)(bias + k0 + ak);
                v.x = fmaxf(dv * (av.x + gv.x) + bv.x, 0.f);
                v.y = fmaxf(dv * (av.y + gv.y) + bv.y, 0.f);
                v.z = fmaxf(dv * (av.z + gv.z) + bv.z, 0.f);
                v.w = fmaxf(dv * (av.w + gv.w) + bv.w, 0.f);
            } else {
                v = *(const float4*)(A + (size_t)grow * 128 + k0 + ak);
            }
        }
        return v;
    };
    auto gloadB = [&](int k0) -> float4 {
        if (!bAct) return make_float4(0.f, 0.f, 0.f, 0.f);
        return *(const float4*)(B + (size_t)(k0 + bk) * BN + bc4 * 4);
    };
    auto storeA = [&](int buf, float4 v) {
        As[buf][ak + 0][am] = v.x;
        As[buf][ak + 1][am] = v.y;
        As[buf][ak + 2][am] = v.z;
        As[buf][ak + 3][am] = v.w;
    };
    auto storeB = [&](int buf, float4 v) {
        if (bAct) *(float4*)(&Bs[buf][bk][bc4 * 4]) = v;
    };

    // prologue: stage 0
    storeA(0, gloadA(0));
    storeB(0, gloadB(0));
    __syncthreads();

#pragma unroll 1
    for (int t = 0; t < 16; t++) {
        const int cur = t & 1;
        float4 pa, pb;
        if (t < 15) {                      // register-staged prefetch
            pa = gloadA((t + 1) * 8);
            pb = gloadB((t + 1) * 8);
        }
        // compute on stage `cur`
#pragma unroll
        for (int k = 0; k < 8; k++) {
            float a[8];
            float4 a0 = *(const float4*)(&As[cur][k][ty * 8]);
            float4 a1 = *(const float4*)(&As[cur][k][ty * 8 + 4]);
            a[0] = a0.x; a[1] = a0.y; a[2] = a0.z; a[3] = a0.w;
            a[4] = a1.x; a[5] = a1.y; a[6] = a1.z; a[7] = a1.w;
            float b[TN];
            if (TN == 8) {
                float4 b0 = *(const float4*)(&Bs[cur][k][tx * 8]);
                float4 b1 = *(const float4*)(&Bs[cur][k][tx * 8 + 4]);
                b[0] = b0.x; b[1] = b0.y; b[2] = b0.z; b[3] = b0.w;
                b[4] = b1.x; b[5] = b1.y; b[6] = b1.z; b[7] = b1.w;
            } else {
                float4 b0 = *(const float4*)(&Bs[cur][k][tx * TN]);
                b[0] = b0.x; b[1] = b0.y; b[2] = b0.z; b[3] = b0.w;
            }
#pragma unroll
            for (int i = 0; i < 8; i++)
#pragma unroll
                for (int j = 0; j < TN; j++) acc[i][j] += a[i] * b[j];
        }
        if (t < 15) {
            storeA(cur ^ 1, pa);
            storeB(cur ^ 1, pb);
        }
        __syncthreads();
    }

    // epilogue: scale by dinv[row], vector stores
#pragma unroll
    for (int i = 0; i < 8; i++) {
        int grow = row0 + ty * 8 + i;
        if (grow >= M) break;
        float d = g_dinv[grow];
        float* out = C + (size_t)grow * BN + tx * TN;
#pragma unroll
        for (int j4 = 0; j4 < TN / 4; j4++) {
            float4 v;
            v.x = d * acc[i][j4 * 4 + 0];
            v.y = d * acc[i][j4 * 4 + 1];
            v.z = d * acc[i][j4 * 4 + 2];
            v.w = d * acc[i][j4 * 4 + 3];
            *(float4*)(out + j4 * 4) = v;
        }
    }
}

// ---------------- scatter layer 1: acc1[dst] += g1[src] (128 floats/edge) ----------------
__global__ void scatter1_kernel(const int* __restrict__ src,
                                const int* __restrict__ dst,
                                int E) {
    int warp = (blockIdx.x * blockDim.x + threadIdx.x) >> 5;
    int lane = threadIdx.x & 31;
    if (warp >= E) return;
    int s = src[warp];
    int d = dst[warp];
    float4 v = ((const float4*)(g_g1 + (size_t)s * HID_C))[lane];
    red_add_v4(g_acc1 + (size_t)d * HID_C + lane * 4, v);
}

// ---------------- scatter layer 2: acc2[dst] += g2[src] (64 floats/edge) ----------------
__global__ void scatter2_kernel(const int* __restrict__ src,
                                const int* __restrict__ dst,
                                int E) {
    int t = blockIdx.x * blockDim.x + threadIdx.x;
    int e = t >> 4;
    int lane = t & 15;
    if (e >= E) return;
    int s = src[e];
    int d = dst[e];
    float4 v = ((const float4*)(g_g2 + (size_t)s * OUT_C))[lane];
    red_add_v4(g_acc2 + (size_t)d * OUT_C + lane * 4, v);
}

// ---------------- pool: out2 = dinv*(acc2+g2)+b2; RED into graph sums ----------------
__global__ void pool_kernel(const int* __restrict__ batch,
                            const float* __restrict__ b2,
                            int N) {
    int t = blockIdx.x * blockDim.x + threadIdx.x;
    int node = t >> 4;
    int lane = t & 15;
    if (node >= N) return;
    int b = batch[node];
    float dv = g_dinv[node];
    float4 av = ((const float4*)(g_acc2 + (size_t)node * OUT_C))[lane];
    float4 gv = ((const float4*)(g_g2   + (size_t)node * OUT_C))[lane];
    float4 bv = *(const float4*)(b2 + lane * 4);
    float4 r;
    r.x = dv * (av.x + gv.x) + bv.x;
    r.y = dv * (av.y + gv.y) + bv.y;
    r.z = dv * (av.z + gv.z) + bv.z;
    r.w = dv * (av.w + gv.w) + bv.w;
    red_add_v4(g_gsum + b * OUT_C + lane * 4, r);
    if (lane == 0) atomicAdd(&g_gcnt[b], 1.0f);
}

__global__ void divide_kernel(float* __restrict__ out, int G) {
    int i = blockIdx.x * blockDim.x + threadIdx.x;
    if (i < G * OUT_C) {
        float c = g_gcnt[i / OUT_C];
        out[i] = g_gsum[i] / fmaxf(c, 1.0f);
    }
}

// ---------------- launch ----------------
extern "C" void kernel_launch(void* const* d_in, const int* in_sizes, int n_in,
                              void* d_out, int out_size) {
    const float* x   = (const float*)d_in[0];
    const float* W1  = (const float*)d_in[1];
    const float* b1  = (const float*)d_in[2];
    const float* W2  = (const float*)d_in[3];
    const float* b2  = (const float*)d_in[4];
    const int*   ei  = (const int*)d_in[5];   // int32
    const int*   bat = (const int*)d_in[6];

    const int N = in_sizes[0] / IN_C;      // 50000
    const int E = in_sizes[5] / 2;         // 625000
    const int G = out_size / OUT_C;        // 128

    const int* src = ei;
    const int* dst = ei + E;

    void *p_degi, *p_acc1, *p_acc2, *p_gsum, *p_gcnt, *p_g1, *p_g2;
    cudaGetSymbolAddress(&p_degi, g_degi);
    cudaGetSymbolAddress(&p_acc1, g_acc1);
    cudaGetSymbolAddress(&p_acc2, g_acc2);
    cudaGetSymbolAddress(&p_gsum, g_gsum);
    cudaGetSymbolAddress(&p_gcnt, g_gcnt);
    cudaGetSymbolAddress(&p_g1, g_g1);
    cudaGetSymbolAddress(&p_g2, g_g2);

    cudaMemsetAsync(p_degi, 0, (size_t)N * sizeof(int));
    cudaMemsetAsync(p_acc1, 0, (size_t)N * HID_C * sizeof(float));
    cudaMemsetAsync(p_acc2, 0, (size_t)N * OUT_C * sizeof(float));
    cudaMemsetAsync(p_gsum, 0, (size_t)G * OUT_C * sizeof(float));
    cudaMemsetAsync(p_gcnt, 0, (size_t)G * sizeof(float));

    deg_kernel <<<(E + 255) / 256, 256>>>(dst, E);
    dinv_kernel<<<(N + 255) / 256, 256>>>(N);

    // GEMM1: g1 = dinv * (x @ W1)
    sgemm_kernel<128, 8, false><<<(N + 127) / 128, 256>>>(x, nullptr, W1, (float*)p_g1, N);
    scatter1_kernel<<<(E + 7) / 8, 256>>>(src, dst, E);

    // GEMM2: g2 = dinv * (relu(dinv*(acc1+g1)+b1) @ W2)  (input fused)
    sgemm_kernel<64, 4, true><<<(N + 127) / 128, 256>>>(nullptr, b1, W2, (float*)p_g2, N);
    scatter2_kernel<<<(E + 15) / 16, 256>>>(src, dst, E);

    pool_kernel<<<(N + 15) / 16, 256>>>(bat, b2, N);
    divide_kernel<<<(G * OUT_C + 255) / 256, 256>>>((float*)d_out, G);
}